// round 1
// baseline (speedup 1.0000x reference)
#include <cuda_runtime.h>

// RBF trainable activation:
//   out[b,c,h,w] = sum_j w[c,j] * exp(-(x[b,c,h,w]-mu_j)^2 / (2 sigma^2))
// with mu_j = linspace(-1,1,63), sigma = 1/31.
//
// Strategy: per-channel 1D function -> cubic Hermite LUT (512 intervals over
// [-1.3, 1.3], analytic derivatives). Outside that range the function is
// < 2e-18 (nearest knot >= 9.3 sigma away), so clamping is exact in fp32.

#define NW 63
#define NCH 64
#define NODES 513
#define NINTERVALS 512
#define HW 9216              // 96*96
#define SLABS 1024           // 16*64

// LUT x-range
#define XLO (-1.30f)
#define XHI (1.30f)
#define HSTEP ((XHI - XLO) / (float)NINTERVALS)   // 0.00507812
#define INV_H ((float)NINTERVALS / (XHI - XLO))   // 196.9230...

// sigma = 1/31 -> 1/(2 sigma^2) = 480.5, 1/sigma^2 = 961
#define INV_2S2 480.5f
#define INV_S2  961.0f
#define SIG     (1.0f / 31.0f)

// Node scratch: (f, f') at 513 nodes per channel.
static __device__ float2 g_nodes[NCH][NODES];

// ---------------------------------------------------------------------------
// Kernel A: evaluate f and f' at LUT nodes (windowed: knots beyond 8 sigma
// contribute < exp(-32) ~ 1e-14, negligible vs 1e-3 tolerance).
// ---------------------------------------------------------------------------
__global__ void build_nodes_kernel(const float* __restrict__ w) {
    int c = blockIdx.x;
    int n = blockIdx.y * blockDim.x + threadIdx.x;
    if (n >= NODES) return;

    float x = XLO + (float)n * HSTEP;
    // knot index position of x: jc = (x - (-1)) / sigma
    float jc = (x + 1.0f) * 31.0f;
    int j0 = (int)ceilf(jc - 8.0f);
    int j1 = (int)floorf(jc + 8.0f);
    if (j0 < 0) j0 = 0;
    if (j1 > NW - 1) j1 = NW - 1;

    float f = 0.0f, fp = 0.0f;
    for (int j = j0; j <= j1; ++j) {
        float mu = -1.0f + (float)j * SIG;
        float d = x - mu;
        float e = __expf(-INV_2S2 * d * d) * w[c * NW + j];
        f += e;
        fp -= INV_S2 * d * e;   // d/dx of the Gaussian times weight
    }
    g_nodes[c][n] = make_float2(f, fp);
}

// ---------------------------------------------------------------------------
// Kernel B: per (batch, channel) slab. Prologue converts Hermite nodes to
// per-interval power-basis coefficients in shared memory (one LDS.128 +
// 3 FMA per element in the main loop), then streams the 9216-element slab
// as float4.
// ---------------------------------------------------------------------------
__device__ __forceinline__ float eval_one(float v, const float4* __restrict__ coef) {
    float t = (v - XLO) * INV_H;
    t = fminf(fmaxf(t, 0.0f), 511.999f);
    int idx = (int)t;
    float fr = t - (float)idx;
    float4 cf = coef[idx];
    return fmaf(fmaf(fmaf(cf.w, fr, cf.z), fr, cf.y), fr, cf.x);
}

__global__ void __launch_bounds__(256) rbf_act_kernel(const float* __restrict__ x,
                                                      float* __restrict__ out) {
    __shared__ float4 coef[NINTERVALS];

    int s = blockIdx.x;          // slab = b*64 + c, matches linear memory order
    int c = s & (NCH - 1);
    int tid = threadIdx.x;

    // Build per-interval cubic coefficients: p(t) = a + b t + c t^2 + d t^3,
    // t in [0,1). Hermite with derivative scaled by interval width.
    for (int i = tid; i < NINTERVALS; i += 256) {
        float2 n0 = g_nodes[c][i];
        float2 n1 = g_nodes[c][i + 1];
        float f0 = n0.x, f1 = n1.x;
        float m0 = n0.y * HSTEP, m1 = n1.y * HSTEP;
        float del = f1 - f0;
        coef[i] = make_float4(f0,
                              m0,
                              3.0f * del - 2.0f * m0 - m1,
                              -2.0f * del + m0 + m1);
    }
    __syncthreads();

    const float4* __restrict__ xin = (const float4*)(x + (size_t)s * HW);
    float4* __restrict__ o = (float4*)(out + (size_t)s * HW);

    // 9216 / 4 = 2304 float4 per slab; 9 iterations of 256 threads.
    #pragma unroll 3
    for (int i = tid; i < HW / 4; i += 256) {
        float4 v = xin[i];
        float4 r;
        r.x = eval_one(v.x, coef);
        r.y = eval_one(v.y, coef);
        r.z = eval_one(v.z, coef);
        r.w = eval_one(v.w, coef);
        o[i] = r;
    }
}

// ---------------------------------------------------------------------------
extern "C" void kernel_launch(void* const* d_in, const int* in_sizes, int n_in,
                              void* d_out, int out_size) {
    const float* x = (const float*)d_in[0];
    const float* w = (const float*)d_in[1];
    // Defensive: identify weight by its element count (64*63 = 4032).
    if (in_sizes[0] == NCH * NW) {
        x = (const float*)d_in[1];
        w = (const float*)d_in[0];
    }

    // 64 channels x 3 blocks of 192 threads covers 513 nodes.
    build_nodes_kernel<<<dim3(NCH, 3), 192>>>(w);
    rbf_act_kernel<<<SLABS, 256>>>(x, (float*)d_out);
}